// round 10
// baseline (speedup 1.0000x reference)
#include <cuda_runtime.h>
#include <cuda_bf16.h>

#define BATCH   16384
#define EMBED   64
#define N_EDGES 524288
#define FULL    0xffffffffu
#define MLPGRID 592

// Fused scratch: [acc 4MB | cnt 64KB] zeroed by one graph memset node.
// g_self is fully overwritten each launch -> needs no zeroing.
__device__ float g_scratch[BATCH * EMBED + BATCH];
__device__ float g_self[BATCH * EMBED];       // gathered self features
#define G_ACC g_scratch
#define G_CNT (g_scratch + BATCH * EMBED)

// ---------------------------------------------------------------------------
// Kernel 1: edge aggregation + self-feature gather.
// The self gather (features[nodes[b]]) is independent of the segment sums,
// so it rides inside this latency-bound kernel's memory shadow: 2048 blocks
// x 256 threads x 2 elements = exactly BATCH*EMBED. 64 consecutive threads
// write one row -> coalesced 256B loads/stores. The MLP then reads g_self
// sequentially from a warm L2 instead of doing a cold random gather.
// Edge loop: R2 design (warp owns 32 edges, ids coalesced+shfl, 8 row loads
// in flight via .cg, register run-compression, atomic flush on change).
// ---------------------------------------------------------------------------
__global__ void agg_kernel(const int*   __restrict__ nodes,
                           const int*   __restrict__ neigh_ids,
                           const int*   __restrict__ seg_ids,
                           const float* __restrict__ features) {
    const int gtid = blockIdx.x * blockDim.x + threadIdx.x;
    const int lane = threadIdx.x & 31;

    // ---- self-feature gather (independent work, overlapped) ----
    #pragma unroll
    for (int t = 0; t < 2; ++t) {
        const int i = gtid + t * (N_EDGES);       // 524288 threads total
        const int b = i >> 6;
        const int j = i & 63;
        g_self[i] = __ldcg(&features[(size_t)nodes[b] * EMBED + j]);
    }

    // ---- edge aggregation ----
    const int warp = gtid >> 5;
    const int e0 = warp * 32;

    const int my_seg = __ldcs(&seg_ids[e0 + lane]);    // streamed once
    const int my_nid = __ldcs(&neigh_ids[e0 + lane]);

    const float2* __restrict__ feats2 = (const float2*)features;

    float2 acc = make_float2(0.0f, 0.0f);
    int cur = __shfl_sync(FULL, my_seg, 0);
    int runlen = 0;

    #pragma unroll
    for (int c = 0; c < 32; c += 8) {
        int    n[8], s[8];
        float2 v[8];
        #pragma unroll
        for (int u = 0; u < 8; ++u) n[u] = __shfl_sync(FULL, my_nid, c + u);
        #pragma unroll
        for (int u = 0; u < 8; ++u)
            v[u] = __ldcg(&feats2[(size_t)n[u] * 32 + lane]);  // L2-only
        #pragma unroll
        for (int u = 0; u < 8; ++u) s[u] = __shfl_sync(FULL, my_seg, c + u);
        #pragma unroll
        for (int u = 0; u < 8; ++u) {
            if (s[u] != cur) {            // warp-uniform (s is broadcast)
                atomicAdd(&G_ACC[cur * EMBED + 2 * lane],     acc.x);
                atomicAdd(&G_ACC[cur * EMBED + 2 * lane + 1], acc.y);
                if (lane == 0) atomicAdd(&G_CNT[cur], (float)runlen);
                acc = make_float2(0.0f, 0.0f);
                cur = s[u];
                runlen = 0;
            }
            acc.x += v[u].x;
            acc.y += v[u].y;
            ++runlen;
        }
    }
    atomicAdd(&G_ACC[cur * EMBED + 2 * lane],     acc.x);
    atomicAdd(&G_ACC[cur * EMBED + 2 * lane + 1], acc.y);
    if (lane == 0) atomicAdd(&G_CNT[cur], (float)runlen);
}

// ---------------------------------------------------------------------------
// Kernel 2: mean + [self|neigh] @ w1^T + b1, relu.
// Inputs (g_self, g_acc, g_cnt) are all sequential and L2-warm (written by
// the agg kernel just before). Register-tiled weights + packed f32x2 FMA,
// double-buffered comb with 1-iteration prefetch.
// ---------------------------------------------------------------------------
__global__ void __launch_bounds__(256)
mlp_kernel(const float* __restrict__ w1,
           const float* __restrict__ b1,
           float*       __restrict__ out) {
    __shared__ union {
        float w1s[64 * 129];                        // staging (prologue only)
        struct {
            __align__(16) float comb[2][4][128];    // double-buffered concat
            float part[4][64 * 5];                  // stride-5 padded partials
        } run;
    } sm;
    __shared__ float b1s[64];

    const int tid = threadIdx.x;
    const int g = tid >> 6;                         // k-group 0..3
    const int j = tid & 63;                         // output dim
    const int r = g;                                // row for fill/writeback

    // ---- prologue: stage w1, fill weight registers, release w1s ----
    for (int idx = tid; idx < 64 * 128; idx += 256) {
        const int jj = idx >> 7;
        const int kk = idx & 127;
        sm.w1s[jj * 129 + kk] = w1[idx];            // w1 row-major (64,128)
    }
    if (tid < 64) b1s[tid] = b1[tid];
    __syncthreads();

    unsigned long long w2[16];
    #pragma unroll
    for (int kk = 0; kk < 16; ++kk) {
        const float lo = sm.w1s[j * 129 + g * 32 + 2 * kk];
        const float hi = sm.w1s[j * 129 + g * 32 + 2 * kk + 1];
        asm("mov.b64 %0, {%1, %2};" : "=l"(w2[kk]) : "f"(lo), "f"(hi));
    }
    __syncthreads();                                // w1s dead; union reused

    const int stride = MLPGRID * 4;
    const int base0  = blockIdx.x * 4;

    // fill comb[0] for iter 0
    {
        const int b = base0 + r;
        sm.run.comb[0][r][j]      = __ldcg(&g_self[b * EMBED + j]);
        const float c = G_CNT[b];
        sm.run.comb[0][r][64 + j] = G_ACC[b * EMBED + j] * (1.0f / fmaxf(c, 1.0f));
    }
    __syncthreads();

    int cur = 0;
    for (int base = base0; base < BATCH; base += stride) {
        const int base1 = base + stride;

        // prefetch next iteration (overlaps the FMA block below)
        float fN = 0.0f, aN = 0.0f;
        if (base1 < BATCH) {
            const int b1 = base1 + r;
            fN = __ldcg(&g_self[b1 * EMBED + j]);
            const float c1 = G_CNT[b1];
            aN = G_ACC[b1 * EMBED + j] * (1.0f / fmaxf(c1, 1.0f));
        }

        // partials from comb[cur] (packed f32x2 FMA)
        #pragma unroll
        for (int rr = 0; rr < 4; ++rr) {
            const ulonglong2* c2 = (const ulonglong2*)&sm.run.comb[cur][rr][g * 32];
            unsigned long long acc = 0ull;          // packed {0.f, 0.f}
            #pragma unroll
            for (int q = 0; q < 8; ++q) {           // 8 x LDS.128 broadcast
                const ulonglong2 c = c2[q];
                asm("fma.rn.f32x2 %0, %1, %2, %0;"
                    : "+l"(acc) : "l"(c.x), "l"(w2[2 * q]));
                asm("fma.rn.f32x2 %0, %1, %2, %0;"
                    : "+l"(acc) : "l"(c.y), "l"(w2[2 * q + 1]));
            }
            float lo, hi;
            asm("mov.b64 {%0, %1}, %2;" : "=f"(lo), "=f"(hi) : "l"(acc));
            sm.run.part[rr][j * 5 + g] = lo + hi;   // conflict-free (5⊥32)
        }
        __syncthreads();

        // reduce + bias + relu + store
        {
            const float s = sm.run.part[r][j * 5 + 0] + sm.run.part[r][j * 5 + 1] +
                            sm.run.part[r][j * 5 + 2] + sm.run.part[r][j * 5 + 3] +
                            b1s[j];
            out[(size_t)(base + r) * EMBED + j] = fmaxf(s, 0.0f);
        }
        if (base1 < BATCH) {
            sm.run.comb[cur ^ 1][r][j]      = fN;
            sm.run.comb[cur ^ 1][r][64 + j] = aN;
        }
        __syncthreads();
        cur ^= 1;
    }
}

// ---------------------------------------------------------------------------
// Launch — memset node + 2 kernels.
// inputs: nodes(i32,16384) neigh_ids(i32,524288) seg_ids(i32,524288)
//         features(f32,64M) w1(f32,8192) b1(f32,64)   output: f32 (16384,64)
// ---------------------------------------------------------------------------
extern "C" void kernel_launch(void* const* d_in, const int* in_sizes, int n_in,
                              void* d_out, int out_size) {
    const int*   nodes     = (const int*)  d_in[0];
    const int*   neigh_ids = (const int*)  d_in[1];
    const int*   seg_ids   = (const int*)  d_in[2];
    const float* features  = (const float*)d_in[3];
    const float* w1        = (const float*)d_in[4];
    const float* b1        = (const float*)d_in[5];
    float*       out       = (float*)d_out;

    void* scratch_ptr = nullptr;
    cudaGetSymbolAddress(&scratch_ptr, g_scratch);
    cudaMemsetAsync(scratch_ptr, 0,
                    (size_t)(BATCH * EMBED + BATCH) * sizeof(float), 0);

    const int n_warps = N_EDGES / 32;             // 16384 warps, 2048 blocks
    agg_kernel<<<n_warps / 8, 256>>>(nodes, neigh_ids, seg_ids, features);

    mlp_kernel<<<MLPGRID, 256>>>(w1, b1, out);
}

// round 11
// speedup vs baseline: 1.0475x; 1.0475x over previous
#include <cuda_runtime.h>
#include <cuda_bf16.h>

#define BATCH   16384
#define EMBED   64
#define N_EDGES 524288
#define FULL    0xffffffffu
#define MLPGRID 592
#define GATHER_BLKS 64          // dedicated self-gather blocks (run first)

// Fused scratch: [acc 4MB | cnt 64KB] zeroed by one graph memset node.
// g_self is fully overwritten each launch -> needs no zeroing.
__device__ float g_scratch[BATCH * EMBED + BATCH];
__device__ float g_self[BATCH * EMBED];       // gathered self features
#define G_ACC g_scratch
#define G_CNT (g_scratch + BATCH * EMBED)

// ---------------------------------------------------------------------------
// Kernel 1: role-split grid.
//   blockIdx <  GATHER_BLKS : self-feature gather (features[nodes[b]] ->
//       g_self). 16K threads x 64 elems, 8-deep load batches, nodes[b] is
//       warp-broadcast. Runs CONCURRENTLY with the edge blocks (scheduled
//       first) -> the 4MB random gather hides in the same memory shadow
//       without serializing any edge warp (R10's mistake).
//   blockIdx >= GATHER_BLKS : edge aggregation (R2/R9 design — proven):
//       warp owns 32 edges, ids coalesced (.cs) + shfl broadcast, 8
//       independent 256B row loads in flight (.cg), register run-compression
//       on sorted seg_ids, atomic flush only on segment change.
// ---------------------------------------------------------------------------
__global__ void agg_kernel(const int*   __restrict__ nodes,
                           const int*   __restrict__ neigh_ids,
                           const int*   __restrict__ seg_ids,
                           const float* __restrict__ features) {
    if (blockIdx.x < GATHER_BLKS) {
        // ---- self-feature gather role ----
        const int t = blockIdx.x * 256 + threadIdx.x;    // 0..16383
        #pragma unroll
        for (int it = 0; it < 64; it += 8) {
            float vv[8];
            #pragma unroll
            for (int u = 0; u < 8; ++u) {                // 8 loads in flight
                const int elem = t + (it + u) * 16384;
                const int b = elem >> 6;                 // warp-broadcast
                const int j = elem & 63;
                vv[u] = __ldcg(&features[(size_t)nodes[b] * EMBED + j]);
            }
            #pragma unroll
            for (int u = 0; u < 8; ++u)
                g_self[t + (it + u) * 16384] = vv[u];    // coalesced
        }
        return;
    }

    // ---- edge aggregation role ----
    const int warp = (blockIdx.x - GATHER_BLKS) * 8 + (threadIdx.x >> 5);
    const int lane = threadIdx.x & 31;
    const int e0 = warp * 32;

    const int my_seg = __ldcs(&seg_ids[e0 + lane]);      // streamed once
    const int my_nid = __ldcs(&neigh_ids[e0 + lane]);

    const float2* __restrict__ feats2 = (const float2*)features;

    float2 acc = make_float2(0.0f, 0.0f);
    int cur = __shfl_sync(FULL, my_seg, 0);
    int runlen = 0;

    #pragma unroll
    for (int c = 0; c < 32; c += 8) {
        int    n[8], s[8];
        float2 v[8];
        #pragma unroll
        for (int u = 0; u < 8; ++u) n[u] = __shfl_sync(FULL, my_nid, c + u);
        #pragma unroll
        for (int u = 0; u < 8; ++u)
            v[u] = __ldcg(&feats2[(size_t)n[u] * 32 + lane]);  // L2-only
        #pragma unroll
        for (int u = 0; u < 8; ++u) s[u] = __shfl_sync(FULL, my_seg, c + u);
        #pragma unroll
        for (int u = 0; u < 8; ++u) {
            if (s[u] != cur) {            // warp-uniform (s is broadcast)
                atomicAdd(&G_ACC[cur * EMBED + 2 * lane],     acc.x);
                atomicAdd(&G_ACC[cur * EMBED + 2 * lane + 1], acc.y);
                if (lane == 0) atomicAdd(&G_CNT[cur], (float)runlen);
                acc = make_float2(0.0f, 0.0f);
                cur = s[u];
                runlen = 0;
            }
            acc.x += v[u].x;
            acc.y += v[u].y;
            ++runlen;
        }
    }
    atomicAdd(&G_ACC[cur * EMBED + 2 * lane],     acc.x);
    atomicAdd(&G_ACC[cur * EMBED + 2 * lane + 1], acc.y);
    if (lane == 0) atomicAdd(&G_CNT[cur], (float)runlen);
}

// ---------------------------------------------------------------------------
// Kernel 2: mean + [self|neigh] @ w1^T + b1, relu. (R10 shape — proven good:
// all inputs sequential + L2-warm.) Register-tiled weights + packed f32x2
// FMA, double-buffered comb with 1-iteration prefetch.
// ---------------------------------------------------------------------------
__global__ void __launch_bounds__(256)
mlp_kernel(const float* __restrict__ w1,
           const float* __restrict__ b1,
           float*       __restrict__ out) {
    __shared__ union {
        float w1s[64 * 129];                        // staging (prologue only)
        struct {
            __align__(16) float comb[2][4][128];    // double-buffered concat
            float part[4][64 * 5];                  // stride-5 padded partials
        } run;
    } sm;
    __shared__ float b1s[64];

    const int tid = threadIdx.x;
    const int g = tid >> 6;                         // k-group 0..3
    const int j = tid & 63;                         // output dim
    const int r = g;                                // row for fill/writeback

    for (int idx = tid; idx < 64 * 128; idx += 256) {
        const int jj = idx >> 7;
        const int kk = idx & 127;
        sm.w1s[jj * 129 + kk] = w1[idx];            // w1 row-major (64,128)
    }
    if (tid < 64) b1s[tid] = b1[tid];
    __syncthreads();

    unsigned long long w2[16];
    #pragma unroll
    for (int kk = 0; kk < 16; ++kk) {
        const float lo = sm.w1s[j * 129 + g * 32 + 2 * kk];
        const float hi = sm.w1s[j * 129 + g * 32 + 2 * kk + 1];
        asm("mov.b64 %0, {%1, %2};" : "=l"(w2[kk]) : "f"(lo), "f"(hi));
    }
    __syncthreads();                                // w1s dead; union reused

    const int stride = MLPGRID * 4;
    const int base0  = blockIdx.x * 4;

    {
        const int b = base0 + r;
        sm.run.comb[0][r][j]      = __ldcg(&g_self[b * EMBED + j]);
        const float c = G_CNT[b];
        sm.run.comb[0][r][64 + j] = G_ACC[b * EMBED + j] * (1.0f / fmaxf(c, 1.0f));
    }
    __syncthreads();

    int cur = 0;
    for (int base = base0; base < BATCH; base += stride) {
        const int base1 = base + stride;

        float fN = 0.0f, aN = 0.0f;
        if (base1 < BATCH) {
            const int b1 = base1 + r;
            fN = __ldcg(&g_self[b1 * EMBED + j]);
            const float c1 = G_CNT[b1];
            aN = G_ACC[b1 * EMBED + j] * (1.0f / fmaxf(c1, 1.0f));
        }

        #pragma unroll
        for (int rr = 0; rr < 4; ++rr) {
            const ulonglong2* c2 = (const ulonglong2*)&sm.run.comb[cur][rr][g * 32];
            unsigned long long acc = 0ull;          // packed {0.f, 0.f}
            #pragma unroll
            for (int q = 0; q < 8; ++q) {           // 8 x LDS.128 broadcast
                const ulonglong2 c = c2[q];
                asm("fma.rn.f32x2 %0, %1, %2, %0;"
                    : "+l"(acc) : "l"(c.x), "l"(w2[2 * q]));
                asm("fma.rn.f32x2 %0, %1, %2, %0;"
                    : "+l"(acc) : "l"(c.y), "l"(w2[2 * q + 1]));
            }
            float lo, hi;
            asm("mov.b64 {%0, %1}, %2;" : "=f"(lo), "=f"(hi) : "l"(acc));
            sm.run.part[rr][j * 5 + g] = lo + hi;   // conflict-free (5⊥32)
        }
        __syncthreads();

        {
            const float s = sm.run.part[r][j * 5 + 0] + sm.run.part[r][j * 5 + 1] +
                            sm.run.part[r][j * 5 + 2] + sm.run.part[r][j * 5 + 3] +
                            b1s[j];
            out[(size_t)(base + r) * EMBED + j] = fmaxf(s, 0.0f);
        }
        if (base1 < BATCH) {
            sm.run.comb[cur ^ 1][r][j]      = fN;
            sm.run.comb[cur ^ 1][r][64 + j] = aN;
        }
        __syncthreads();
        cur ^= 1;
    }
}

// ---------------------------------------------------------------------------
// Launch — memset node + 2 kernels.
// inputs: nodes(i32,16384) neigh_ids(i32,524288) seg_ids(i32,524288)
//         features(f32,64M) w1(f32,8192) b1(f32,64)   output: f32 (16384,64)
// ---------------------------------------------------------------------------
extern "C" void kernel_launch(void* const* d_in, const int* in_sizes, int n_in,
                              void* d_out, int out_size) {
    const int*   nodes     = (const int*)  d_in[0];
    const int*   neigh_ids = (const int*)  d_in[1];
    const int*   seg_ids   = (const int*)  d_in[2];
    const float* features  = (const float*)d_in[3];
    const float* w1        = (const float*)d_in[4];
    const float* b1        = (const float*)d_in[5];
    float*       out       = (float*)d_out;

    void* scratch_ptr = nullptr;
    cudaGetSymbolAddress(&scratch_ptr, g_scratch);
    cudaMemsetAsync(scratch_ptr, 0,
                    (size_t)(BATCH * EMBED + BATCH) * sizeof(float), 0);

    // 64 gather blocks (first) + 2048 edge blocks (16384 warps x 32 edges)
    const int n_blocks = GATHER_BLKS + (N_EDGES / 32) / 8;
    agg_kernel<<<n_blocks, 256>>>(nodes, neigh_ids, seg_ids, features);

    mlp_kernel<<<MLPGRID, 256>>>(w1, b1, out);
}